// round 1
// baseline (speedup 1.0000x reference)
#include <cuda_runtime.h>
#include <math.h>

// ---------------- static scratch (no allocations allowed) ----------------
#define MAXN   50048            // 391 * 128, padded
#define MAXE   800000

__device__ float g_x0[MAXN * 128];
__device__ float g_x1[MAXN * 128];
__device__ float g_agg[(size_t)MAXN * 768];
__device__ float g_t[MAXN * 8];          // [N,6] padded to 8 for float4 loads
__device__ float g_Wflat[4][768 * 128];  // stacked transposed head weights
__device__ int   g_deg[MAXN];
__device__ int   g_off[MAXN + 1];
__device__ int   g_cur[MAXN];
__device__ int   g_src[MAXE];

// ---------------- CSR construction ----------------
__global__ void k_zero_deg(int n) {
    int i = blockIdx.x * blockDim.x + threadIdx.x;
    if (i < n) g_deg[i] = 0;
}

__global__ void k_hist(const int* __restrict__ ei, int e) {
    int i = blockIdx.x * blockDim.x + threadIdx.x;
    if (i < e) atomicAdd(&g_deg[ei[e + i]], 1);   // row 1 = dst
}

// single-block exclusive scan over g_deg -> g_off, g_cur
__global__ void k_scan(int n) {
    __shared__ int sm[1024];
    __shared__ int base;
    if (threadIdx.x == 0) base = 0;
    __syncthreads();
    for (int start = 0; start < n; start += 1024) {
        int i = start + threadIdx.x;
        int v = (i < n) ? g_deg[i] : 0;
        sm[threadIdx.x] = v;
        __syncthreads();
        for (int ofs = 1; ofs < 1024; ofs <<= 1) {
            int t = 0;
            if ((int)threadIdx.x >= ofs) t = sm[threadIdx.x - ofs];
            __syncthreads();
            sm[threadIdx.x] += t;
            __syncthreads();
        }
        if (i < n) {
            int excl = base + sm[threadIdx.x] - v;
            g_off[i] = excl;
            g_cur[i] = excl;
        }
        int total = sm[1023];
        __syncthreads();
        if (threadIdx.x == 0) base += total;
        __syncthreads();
    }
    if (threadIdx.x == 0) g_off[n] = base;
}

__global__ void k_scatter(const int* __restrict__ ei, int e) {
    int i = blockIdx.x * blockDim.x + threadIdx.x;
    if (i < e) {
        int dst = ei[e + i];
        int p = atomicAdd(&g_cur[dst], 1);
        g_src[p] = ei[i];                 // row 0 = src
    }
}

// ---------------- weight restack: Wflat[(h*128+k)*128 + d] = W[h][d][k] ----------------
__global__ void k_wflat(int l, const float* __restrict__ Wg) {
    int gid = blockIdx.x * blockDim.x + threadIdx.x;
    if (gid >= 6 * 128 * 128) return;
    int krow = gid >> 7;       // 0..767
    int d = gid & 127;
    int h = krow >> 7;
    int kk = krow & 127;
    g_Wflat[l][krow * 128 + d] = Wg[h * 16384 + d * 128 + kk];
}

// ---------------- input layer: x0 = relu([pos,norm] @ w1.T + b1) ----------------
__global__ void k_x0(const float* __restrict__ pos, const float* __restrict__ nrm,
                     const float* __restrict__ w1, const float* __restrict__ b1, int n) {
    int gid = blockIdx.x * blockDim.x + threadIdx.x;
    if (gid >= n * 128) return;
    int i = gid >> 7, d = gid & 127;
    const float* wr = w1 + d * 6;
    float a = b1[d];
    a = fmaf(pos[i * 3 + 0], wr[0], a);
    a = fmaf(pos[i * 3 + 1], wr[1], a);
    a = fmaf(pos[i * 3 + 2], wr[2], a);
    a = fmaf(nrm[i * 3 + 0], wr[3], a);
    a = fmaf(nrm[i * 3 + 1], wr[4], a);
    a = fmaf(nrm[i * 3 + 2], wr[5], a);
    g_x0[(size_t)i * 128 + d] = fmaxf(a, 0.f);
}

// ---------------- t = x @ u.T (per node, warp-per-node) ----------------
__global__ void k_t(int sel, const float* __restrict__ u, int n) {
    int gw = (blockIdx.x * blockDim.x + threadIdx.x) >> 5;
    int lane = threadIdx.x & 31;
    if (gw >= n) return;
    const float* x = sel ? g_x1 : g_x0;
    float4 xv = *(const float4*)(x + (size_t)gw * 128 + lane * 4);
    float a0, a1, a2, a3, a4, a5;
    {
        float4 w;
        w = *(const float4*)(u + 0 * 128 + lane * 4); a0 = xv.x*w.x + xv.y*w.y + xv.z*w.z + xv.w*w.w;
        w = *(const float4*)(u + 1 * 128 + lane * 4); a1 = xv.x*w.x + xv.y*w.y + xv.z*w.z + xv.w*w.w;
        w = *(const float4*)(u + 2 * 128 + lane * 4); a2 = xv.x*w.x + xv.y*w.y + xv.z*w.z + xv.w*w.w;
        w = *(const float4*)(u + 3 * 128 + lane * 4); a3 = xv.x*w.x + xv.y*w.y + xv.z*w.z + xv.w*w.w;
        w = *(const float4*)(u + 4 * 128 + lane * 4); a4 = xv.x*w.x + xv.y*w.y + xv.z*w.z + xv.w*w.w;
        w = *(const float4*)(u + 5 * 128 + lane * 4); a5 = xv.x*w.x + xv.y*w.y + xv.z*w.z + xv.w*w.w;
    }
    #pragma unroll
    for (int o = 16; o; o >>= 1) {
        a0 += __shfl_xor_sync(0xffffffffu, a0, o);
        a1 += __shfl_xor_sync(0xffffffffu, a1, o);
        a2 += __shfl_xor_sync(0xffffffffu, a2, o);
        a3 += __shfl_xor_sync(0xffffffffu, a3, o);
        a4 += __shfl_xor_sync(0xffffffffu, a4, o);
        a5 += __shfl_xor_sync(0xffffffffu, a5, o);
    }
    if (lane == 0) {
        float* tp = g_t + (size_t)gw * 8;
        tp[0] = a0; tp[1] = a1; tp[2] = a2; tp[3] = a3; tp[4] = a4; tp[5] = a5;
        tp[6] = 0.f; tp[7] = 0.f;
    }
}

// ---------------- edge aggregation (warp per dst node, no atomics) ----------------
__global__ void k_agg(int sel, const float* __restrict__ cvec, int n) {
    int gw = (blockIdx.x * blockDim.x + threadIdx.x) >> 5;
    int lane = threadIdx.x & 31;
    if (gw >= n) return;
    const float* x = sel ? g_x1 : g_x0;
    int beg = g_off[gw], end = g_off[gw + 1];
    float4 tI0 = *(const float4*)&g_t[(size_t)gw * 8];
    float4 tI1 = *(const float4*)&g_t[(size_t)gw * 8 + 4];
    float bb0 = cvec[0] - tI0.x, bb1 = cvec[1] - tI0.y, bb2 = cvec[2] - tI0.z;
    float bb3 = cvec[3] - tI0.w, bb4 = cvec[4] - tI1.x, bb5 = cvec[5] - tI1.y;
    float4 a0 = make_float4(0,0,0,0), a1 = a0, a2 = a0, a3 = a0, a4 = a0, a5 = a0;
    for (int ep = beg; ep < end; ep++) {
        int s = g_src[ep];
        float4 ts0 = *(const float4*)&g_t[(size_t)s * 8];
        float4 ts1 = *(const float4*)&g_t[(size_t)s * 8 + 4];
        float s0 = ts0.x + bb0, s1 = ts0.y + bb1, s2 = ts0.z + bb2;
        float s3 = ts0.w + bb3, s4 = ts1.x + bb4, s5 = ts1.y + bb5;
        float mx = fmaxf(fmaxf(fmaxf(s0, s1), fmaxf(s2, s3)), fmaxf(s4, s5));
        float e0 = __expf(s0 - mx), e1 = __expf(s1 - mx), e2 = __expf(s2 - mx);
        float e3 = __expf(s3 - mx), e4 = __expf(s4 - mx), e5 = __expf(s5 - mx);
        float inv = 1.f / (e0 + e1 + e2 + e3 + e4 + e5);
        float4 xv = *(const float4*)(x + (size_t)s * 128 + lane * 4);
        float q;
        q = e0 * inv; a0.x = fmaf(q, xv.x, a0.x); a0.y = fmaf(q, xv.y, a0.y); a0.z = fmaf(q, xv.z, a0.z); a0.w = fmaf(q, xv.w, a0.w);
        q = e1 * inv; a1.x = fmaf(q, xv.x, a1.x); a1.y = fmaf(q, xv.y, a1.y); a1.z = fmaf(q, xv.z, a1.z); a1.w = fmaf(q, xv.w, a1.w);
        q = e2 * inv; a2.x = fmaf(q, xv.x, a2.x); a2.y = fmaf(q, xv.y, a2.y); a2.z = fmaf(q, xv.z, a2.z); a2.w = fmaf(q, xv.w, a2.w);
        q = e3 * inv; a3.x = fmaf(q, xv.x, a3.x); a3.y = fmaf(q, xv.y, a3.y); a3.z = fmaf(q, xv.z, a3.z); a3.w = fmaf(q, xv.w, a3.w);
        q = e4 * inv; a4.x = fmaf(q, xv.x, a4.x); a4.y = fmaf(q, xv.y, a4.y); a4.z = fmaf(q, xv.z, a4.z); a4.w = fmaf(q, xv.w, a4.w);
        q = e5 * inv; a5.x = fmaf(q, xv.x, a5.x); a5.y = fmaf(q, xv.y, a5.y); a5.z = fmaf(q, xv.z, a5.z); a5.w = fmaf(q, xv.w, a5.w);
    }
    float invdeg = 1.f / fmaxf((float)(end - beg), 1.f);
    float* o = g_agg + (size_t)gw * 768 + lane * 4;
    a0.x *= invdeg; a0.y *= invdeg; a0.z *= invdeg; a0.w *= invdeg; *(float4*)(o + 0 * 128) = a0;
    a1.x *= invdeg; a1.y *= invdeg; a1.z *= invdeg; a1.w *= invdeg; *(float4*)(o + 1 * 128) = a1;
    a2.x *= invdeg; a2.y *= invdeg; a2.z *= invdeg; a2.w *= invdeg; *(float4*)(o + 2 * 128) = a2;
    a3.x *= invdeg; a3.y *= invdeg; a3.z *= invdeg; a3.w *= invdeg; *(float4*)(o + 3 * 128) = a3;
    a4.x *= invdeg; a4.y *= invdeg; a4.z *= invdeg; a4.w *= invdeg; *(float4*)(o + 4 * 128) = a4;
    a5.x *= invdeg; a5.y *= invdeg; a5.z *= invdeg; a5.w *= invdeg; *(float4*)(o + 5 * 128) = a5;
}

// ---------------- GEMM: x_next = relu(agg[N,768] @ Wflat[768,128] + bg) ----------------
__global__ void __launch_bounds__(256) k_gemm(int l, const float* __restrict__ bias, int outsel) {
    __shared__ float As[16][128];   // transposed A tile
    __shared__ float Bs[16][128];
    const float* A = g_agg;
    const float* B = g_Wflat[l];
    float* C = outsel ? g_x1 : g_x0;
    int block_row = blockIdx.x * 128;
    int tid = threadIdx.x;
    int tr = tid >> 4, tc = tid & 15;
    float acc[8][8];
    #pragma unroll
    for (int i = 0; i < 8; i++)
        #pragma unroll
        for (int j = 0; j < 8; j++) acc[i][j] = 0.f;

    for (int k0 = 0; k0 < 768; k0 += 16) {
        #pragma unroll
        for (int i = 0; i < 2; i++) {
            int f = tid * 2 + i;
            int r = f >> 2, c4 = f & 3;
            float4 v = *(const float4*)(A + (size_t)(block_row + r) * 768 + k0 + c4 * 4);
            As[c4 * 4 + 0][r] = v.x; As[c4 * 4 + 1][r] = v.y;
            As[c4 * 4 + 2][r] = v.z; As[c4 * 4 + 3][r] = v.w;
        }
        #pragma unroll
        for (int i = 0; i < 2; i++) {
            int f = tid * 2 + i;
            int r = f >> 5, c4 = f & 31;
            *(float4*)&Bs[r][c4 * 4] = *(const float4*)(B + (size_t)(k0 + r) * 128 + c4 * 4);
        }
        __syncthreads();
        #pragma unroll
        for (int k = 0; k < 16; k++) {
            float a[8], b[8];
            *(float4*)&a[0] = *(float4*)&As[k][tr * 8];
            *(float4*)&a[4] = *(float4*)&As[k][tr * 8 + 4];
            *(float4*)&b[0] = *(float4*)&Bs[k][tc * 8];
            *(float4*)&b[4] = *(float4*)&Bs[k][tc * 8 + 4];
            #pragma unroll
            for (int i = 0; i < 8; i++)
                #pragma unroll
                for (int j = 0; j < 8; j++) acc[i][j] = fmaf(a[i], b[j], acc[i][j]);
        }
        __syncthreads();
    }
    #pragma unroll
    for (int i = 0; i < 8; i++) {
        int row = block_row + tr * 8 + i;
        #pragma unroll
        for (int j = 0; j < 8; j += 4) {
            int col = tc * 8 + j;
            float4 v;
            v.x = fmaxf(acc[i][j + 0] + bias[col + 0], 0.f);
            v.y = fmaxf(acc[i][j + 1] + bias[col + 1], 0.f);
            v.z = fmaxf(acc[i][j + 2] + bias[col + 2], 0.f);
            v.w = fmaxf(acc[i][j + 3] + bias[col + 3], 0.f);
            *(float4*)(C + (size_t)row * 128 + col) = v;
        }
    }
}

// ---------------- output: out = x @ w2.T + b2 ----------------
__global__ void k_out(int sel, const float* __restrict__ w2, const float* __restrict__ b2,
                      float* __restrict__ out, int n) {
    int gw = (blockIdx.x * blockDim.x + threadIdx.x) >> 5;
    int lane = threadIdx.x & 31;
    if (gw >= n) return;
    const float* x = sel ? g_x1 : g_x0;
    float4 xv = *(const float4*)(x + (size_t)gw * 128 + lane * 4);
    float4 w;
    w = *(const float4*)(w2 + 0 * 128 + lane * 4);
    float a0 = xv.x * w.x + xv.y * w.y + xv.z * w.z + xv.w * w.w;
    w = *(const float4*)(w2 + 1 * 128 + lane * 4);
    float a1 = xv.x * w.x + xv.y * w.y + xv.z * w.z + xv.w * w.w;
    w = *(const float4*)(w2 + 2 * 128 + lane * 4);
    float a2 = xv.x * w.x + xv.y * w.y + xv.z * w.z + xv.w * w.w;
    #pragma unroll
    for (int o = 16; o; o >>= 1) {
        a0 += __shfl_xor_sync(0xffffffffu, a0, o);
        a1 += __shfl_xor_sync(0xffffffffu, a1, o);
        a2 += __shfl_xor_sync(0xffffffffu, a2, o);
    }
    if (lane == 0) {
        out[(size_t)gw * 3 + 0] = a0 + b2[0];
        out[(size_t)gw * 3 + 1] = a1 + b2[1];
        out[(size_t)gw * 3 + 2] = a2 + b2[2];
    }
}

// ---------------- launch ----------------
extern "C" void kernel_launch(void* const* d_in, const int* in_sizes, int n_in,
                              void* d_out, int out_size) {
    const float* pos = (const float*)d_in[0];
    const float* nrm = (const float*)d_in[1];
    const int*   ei  = (const int*)d_in[2];
    const float* w1  = (const float*)d_in[3];
    const float* b1  = (const float*)d_in[4];
    const float* w2  = (const float*)d_in[5];
    const float* b2  = (const float*)d_in[6];
    const float* Wg[4] = {(const float*)d_in[7],  (const float*)d_in[11],
                          (const float*)d_in[15], (const float*)d_in[19]};
    const float* u[4]  = {(const float*)d_in[8],  (const float*)d_in[12],
                          (const float*)d_in[16], (const float*)d_in[20]};
    const float* c[4]  = {(const float*)d_in[9],  (const float*)d_in[13],
                          (const float*)d_in[17], (const float*)d_in[21]};
    const float* bg[4] = {(const float*)d_in[10], (const float*)d_in[14],
                          (const float*)d_in[18], (const float*)d_in[22]};

    int n = in_sizes[0] / 3;   // 50000
    int e = in_sizes[2] / 2;   // 800000

    // CSR build
    k_zero_deg<<<(n + 255) / 256, 256>>>(n);
    k_hist<<<(e + 255) / 256, 256>>>(ei, e);
    k_scan<<<1, 1024>>>(n);
    k_scatter<<<(e + 255) / 256, 256>>>(ei, e);

    // weight restack (all layers)
    for (int l = 0; l < 4; l++)
        k_wflat<<<(6 * 128 * 128 + 255) / 256, 256>>>(l, Wg[l]);

    // input layer
    k_x0<<<(n * 128 + 255) / 256, 256>>>(pos, nrm, w1, b1, n);

    // 4 feast layers (ping-pong x between g_x0 / g_x1)
    int sel = 0;
    int warp_blocks = (n * 32 + 255) / 256;
    for (int l = 0; l < 4; l++) {
        k_t<<<warp_blocks, 256>>>(sel, u[l], n);
        k_agg<<<warp_blocks, 256>>>(sel, c[l], n);
        k_gemm<<<(n + 127) / 128, 256>>>(l, bg[l], 1 - sel);
        sel = 1 - sel;
    }

    // output projection
    k_out<<<warp_blocks, 256>>>(sel, w2, b2, (float*)d_out, n);
}

// round 2
// speedup vs baseline: 1.0997x; 1.0997x over previous
#include <cuda_runtime.h>
#include <math.h>

// ---------------- static scratch (no allocations allowed) ----------------
#define MAXN   50048            // padded
#define MAXE   800000

__device__ float g_x0[MAXN * 128];
__device__ float g_x1[MAXN * 128];
__device__ float g_agg[(size_t)MAXN * 768];
__device__ float g_t[MAXN * 8];          // [N,6] padded to 8 for float4 loads
__device__ float g_q[(size_t)MAXE * 6];  // per-edge softmax (CSR order), pre-scaled by 1/deg
__device__ float g_Wflat[4][768 * 128];  // stacked transposed head weights
__device__ int   g_deg[MAXN];
__device__ int   g_off[MAXN + 1];
__device__ int   g_cur[MAXN];
__device__ int   g_src[MAXE];            // CSR-ordered source ids
__device__ int   g_dst[MAXE];            // CSR-ordered dest ids (for edgeq)

// ---------------- CSR construction ----------------
__global__ void k_zero_deg(int n) {
    int i = blockIdx.x * blockDim.x + threadIdx.x;
    if (i < n) g_deg[i] = 0;
}

__global__ void k_hist(const int* __restrict__ ei, int e) {
    int i = blockIdx.x * blockDim.x + threadIdx.x;
    if (i < e) atomicAdd(&g_deg[ei[e + i]], 1);   // row 1 = dst
}

// single-block exclusive scan over g_deg -> g_off, g_cur
__global__ void k_scan(int n) {
    __shared__ int sm[1024];
    __shared__ int base;
    if (threadIdx.x == 0) base = 0;
    __syncthreads();
    for (int start = 0; start < n; start += 1024) {
        int i = start + threadIdx.x;
        int v = (i < n) ? g_deg[i] : 0;
        sm[threadIdx.x] = v;
        __syncthreads();
        for (int ofs = 1; ofs < 1024; ofs <<= 1) {
            int t = 0;
            if ((int)threadIdx.x >= ofs) t = sm[threadIdx.x - ofs];
            __syncthreads();
            sm[threadIdx.x] += t;
            __syncthreads();
        }
        if (i < n) {
            int excl = base + sm[threadIdx.x] - v;
            g_off[i] = excl;
            g_cur[i] = excl;
        }
        int total = sm[1023];
        __syncthreads();
        if (threadIdx.x == 0) base += total;
        __syncthreads();
    }
    if (threadIdx.x == 0) g_off[n] = base;
}

__global__ void k_scatter(const int* __restrict__ ei, int e) {
    int i = blockIdx.x * blockDim.x + threadIdx.x;
    if (i < e) {
        int dst = ei[e + i];
        int p = atomicAdd(&g_cur[dst], 1);
        g_src[p] = ei[i];                 // row 0 = src
        g_dst[p] = dst;
    }
}

// ---------------- weight restack: Wflat[(h*128+k)*128 + d] = W[h][d][k] ----------------
__global__ void k_wflat(int l, const float* __restrict__ Wg) {
    int gid = blockIdx.x * blockDim.x + threadIdx.x;
    if (gid >= 6 * 128 * 128) return;
    int krow = gid >> 7;       // 0..767
    int d = gid & 127;
    int h = krow >> 7;
    int kk = krow & 127;
    g_Wflat[l][krow * 128 + d] = Wg[h * 16384 + d * 128 + kk];
}

// ---------------- input layer: x0 = relu([pos,norm] @ w1.T + b1) ----------------
__global__ void k_x0(const float* __restrict__ pos, const float* __restrict__ nrm,
                     const float* __restrict__ w1, const float* __restrict__ b1, int n) {
    int gid = blockIdx.x * blockDim.x + threadIdx.x;
    if (gid >= n * 128) return;
    int i = gid >> 7, d = gid & 127;
    const float* wr = w1 + d * 6;
    float a = b1[d];
    a = fmaf(pos[i * 3 + 0], wr[0], a);
    a = fmaf(pos[i * 3 + 1], wr[1], a);
    a = fmaf(pos[i * 3 + 2], wr[2], a);
    a = fmaf(nrm[i * 3 + 0], wr[3], a);
    a = fmaf(nrm[i * 3 + 1], wr[4], a);
    a = fmaf(nrm[i * 3 + 2], wr[5], a);
    g_x0[(size_t)i * 128 + d] = fmaxf(a, 0.f);
}

// ---------------- t = x @ u.T (per node, warp-per-node) ----------------
__global__ void k_t(int sel, const float* __restrict__ u, int n) {
    int gw = (blockIdx.x * blockDim.x + threadIdx.x) >> 5;
    int lane = threadIdx.x & 31;
    if (gw >= n) return;
    const float* x = sel ? g_x1 : g_x0;
    float4 xv = *(const float4*)(x + (size_t)gw * 128 + lane * 4);
    float a0, a1, a2, a3, a4, a5;
    {
        float4 w;
        w = *(const float4*)(u + 0 * 128 + lane * 4); a0 = xv.x*w.x + xv.y*w.y + xv.z*w.z + xv.w*w.w;
        w = *(const float4*)(u + 1 * 128 + lane * 4); a1 = xv.x*w.x + xv.y*w.y + xv.z*w.z + xv.w*w.w;
        w = *(const float4*)(u + 2 * 128 + lane * 4); a2 = xv.x*w.x + xv.y*w.y + xv.z*w.z + xv.w*w.w;
        w = *(const float4*)(u + 3 * 128 + lane * 4); a3 = xv.x*w.x + xv.y*w.y + xv.z*w.z + xv.w*w.w;
        w = *(const float4*)(u + 4 * 128 + lane * 4); a4 = xv.x*w.x + xv.y*w.y + xv.z*w.z + xv.w*w.w;
        w = *(const float4*)(u + 5 * 128 + lane * 4); a5 = xv.x*w.x + xv.y*w.y + xv.z*w.z + xv.w*w.w;
    }
    #pragma unroll
    for (int o = 16; o; o >>= 1) {
        a0 += __shfl_xor_sync(0xffffffffu, a0, o);
        a1 += __shfl_xor_sync(0xffffffffu, a1, o);
        a2 += __shfl_xor_sync(0xffffffffu, a2, o);
        a3 += __shfl_xor_sync(0xffffffffu, a3, o);
        a4 += __shfl_xor_sync(0xffffffffu, a4, o);
        a5 += __shfl_xor_sync(0xffffffffu, a5, o);
    }
    if (lane == 0) {
        float* tp = g_t + (size_t)gw * 8;
        tp[0] = a0; tp[1] = a1; tp[2] = a2; tp[3] = a3; tp[4] = a4; tp[5] = a5;
        tp[6] = 0.f; tp[7] = 0.f;
    }
}

// ---------------- per-edge softmax (one thread per CSR slot), q pre-scaled by 1/deg ----------------
__global__ void k_edgeq(const float* __restrict__ cvec, int e) {
    int i = blockIdx.x * blockDim.x + threadIdx.x;
    if (i >= e) return;
    int s = g_src[i], d = g_dst[i];
    float4 ts0 = *(const float4*)&g_t[(size_t)s * 8];
    float4 ts1 = *(const float4*)&g_t[(size_t)s * 8 + 4];
    float4 td0 = *(const float4*)&g_t[(size_t)d * 8];
    float4 td1 = *(const float4*)&g_t[(size_t)d * 8 + 4];
    float s0 = ts0.x - td0.x + cvec[0];
    float s1 = ts0.y - td0.y + cvec[1];
    float s2 = ts0.z - td0.z + cvec[2];
    float s3 = ts0.w - td0.w + cvec[3];
    float s4 = ts1.x - td1.x + cvec[4];
    float s5 = ts1.y - td1.y + cvec[5];
    float mx = fmaxf(fmaxf(fmaxf(s0, s1), fmaxf(s2, s3)), fmaxf(s4, s5));
    float e0 = __expf(s0 - mx), e1 = __expf(s1 - mx), e2 = __expf(s2 - mx);
    float e3 = __expf(s3 - mx), e4 = __expf(s4 - mx), e5 = __expf(s5 - mx);
    int deg = g_off[d + 1] - g_off[d];
    float inv = 1.f / ((e0 + e1 + e2 + e3 + e4 + e5) * fmaxf((float)deg, 1.f));
    float* qp = g_q + (size_t)i * 6;
    qp[0] = e0 * inv; qp[1] = e1 * inv; qp[2] = e2 * inv;
    qp[3] = e3 * inv; qp[4] = e4 * inv; qp[5] = e5 * inv;
}

// ---------------- edge aggregation (warp per dst node, no atomics, no softmax) ----------------
__global__ void k_agg(int sel, int n) {
    int gw = (blockIdx.x * blockDim.x + threadIdx.x) >> 5;
    int lane = threadIdx.x & 31;
    if (gw >= n) return;
    const float* x = sel ? g_x1 : g_x0;
    int beg = g_off[gw], end = g_off[gw + 1];
    float4 a0 = make_float4(0,0,0,0), a1 = a0, a2 = a0, a3 = a0, a4 = a0, a5 = a0;
    for (int ep = beg; ep < end; ep++) {
        int s = g_src[ep];
        const float* qp = g_q + (size_t)ep * 6;
        float q0 = qp[0], q1 = qp[1], q2 = qp[2], q3 = qp[3], q4 = qp[4], q5 = qp[5];
        float4 xv = *(const float4*)(x + (size_t)s * 128 + lane * 4);
        a0.x = fmaf(q0, xv.x, a0.x); a0.y = fmaf(q0, xv.y, a0.y); a0.z = fmaf(q0, xv.z, a0.z); a0.w = fmaf(q0, xv.w, a0.w);
        a1.x = fmaf(q1, xv.x, a1.x); a1.y = fmaf(q1, xv.y, a1.y); a1.z = fmaf(q1, xv.z, a1.z); a1.w = fmaf(q1, xv.w, a1.w);
        a2.x = fmaf(q2, xv.x, a2.x); a2.y = fmaf(q2, xv.y, a2.y); a2.z = fmaf(q2, xv.z, a2.z); a2.w = fmaf(q2, xv.w, a2.w);
        a3.x = fmaf(q3, xv.x, a3.x); a3.y = fmaf(q3, xv.y, a3.y); a3.z = fmaf(q3, xv.z, a3.z); a3.w = fmaf(q3, xv.w, a3.w);
        a4.x = fmaf(q4, xv.x, a4.x); a4.y = fmaf(q4, xv.y, a4.y); a4.z = fmaf(q4, xv.z, a4.z); a4.w = fmaf(q4, xv.w, a4.w);
        a5.x = fmaf(q5, xv.x, a5.x); a5.y = fmaf(q5, xv.y, a5.y); a5.z = fmaf(q5, xv.z, a5.z); a5.w = fmaf(q5, xv.w, a5.w);
    }
    float* o = g_agg + (size_t)gw * 768 + lane * 4;
    *(float4*)(o + 0 * 128) = a0;
    *(float4*)(o + 1 * 128) = a1;
    *(float4*)(o + 2 * 128) = a2;
    *(float4*)(o + 3 * 128) = a3;
    *(float4*)(o + 4 * 128) = a4;
    *(float4*)(o + 5 * 128) = a5;
}

// ---------------- GEMM: x_next = relu(agg[N,768] @ Wflat[768,128] + bg) ----------------
__global__ void __launch_bounds__(256) k_gemm(int l, const float* __restrict__ bias, int outsel) {
    __shared__ float As[16][128];   // transposed A tile
    __shared__ float Bs[16][128];
    const float* A = g_agg;
    const float* B = g_Wflat[l];
    float* C = outsel ? g_x1 : g_x0;
    int block_row = blockIdx.x * 128;
    int tid = threadIdx.x;
    int tr = tid >> 4, tc = tid & 15;
    float acc[8][8];
    #pragma unroll
    for (int i = 0; i < 8; i++)
        #pragma unroll
        for (int j = 0; j < 8; j++) acc[i][j] = 0.f;

    for (int k0 = 0; k0 < 768; k0 += 16) {
        #pragma unroll
        for (int i = 0; i < 2; i++) {
            int f = tid * 2 + i;
            int r = f >> 2, c4 = f & 3;
            float4 v = *(const float4*)(A + (size_t)(block_row + r) * 768 + k0 + c4 * 4);
            As[c4 * 4 + 0][r] = v.x; As[c4 * 4 + 1][r] = v.y;
            As[c4 * 4 + 2][r] = v.z; As[c4 * 4 + 3][r] = v.w;
        }
        #pragma unroll
        for (int i = 0; i < 2; i++) {
            int f = tid * 2 + i;
            int r = f >> 5, c4 = f & 31;
            *(float4*)&Bs[r][c4 * 4] = *(const float4*)(B + (size_t)(k0 + r) * 128 + c4 * 4);
        }
        __syncthreads();
        #pragma unroll
        for (int k = 0; k < 16; k++) {
            float a[8], b[8];
            *(float4*)&a[0] = *(float4*)&As[k][tr * 8];
            *(float4*)&a[4] = *(float4*)&As[k][tr * 8 + 4];
            *(float4*)&b[0] = *(float4*)&Bs[k][tc * 8];
            *(float4*)&b[4] = *(float4*)&Bs[k][tc * 8 + 4];
            #pragma unroll
            for (int i = 0; i < 8; i++)
                #pragma unroll
                for (int j = 0; j < 8; j++) acc[i][j] = fmaf(a[i], b[j], acc[i][j]);
        }
        __syncthreads();
    }
    #pragma unroll
    for (int i = 0; i < 8; i++) {
        int row = block_row + tr * 8 + i;
        #pragma unroll
        for (int j = 0; j < 8; j += 4) {
            int col = tc * 8 + j;
            float4 v;
            v.x = fmaxf(acc[i][j + 0] + bias[col + 0], 0.f);
            v.y = fmaxf(acc[i][j + 1] + bias[col + 1], 0.f);
            v.z = fmaxf(acc[i][j + 2] + bias[col + 2], 0.f);
            v.w = fmaxf(acc[i][j + 3] + bias[col + 3], 0.f);
            *(float4*)(C + (size_t)row * 128 + col) = v;
        }
    }
}

// ---------------- output: out = x @ w2.T + b2 ----------------
__global__ void k_out(int sel, const float* __restrict__ w2, const float* __restrict__ b2,
                      float* __restrict__ out, int n) {
    int gw = (blockIdx.x * blockDim.x + threadIdx.x) >> 5;
    int lane = threadIdx.x & 31;
    if (gw >= n) return;
    const float* x = sel ? g_x1 : g_x0;
    float4 xv = *(const float4*)(x + (size_t)gw * 128 + lane * 4);
    float4 w;
    w = *(const float4*)(w2 + 0 * 128 + lane * 4);
    float a0 = xv.x * w.x + xv.y * w.y + xv.z * w.z + xv.w * w.w;
    w = *(const float4*)(w2 + 1 * 128 + lane * 4);
    float a1 = xv.x * w.x + xv.y * w.y + xv.z * w.z + xv.w * w.w;
    w = *(const float4*)(w2 + 2 * 128 + lane * 4);
    float a2 = xv.x * w.x + xv.y * w.y + xv.z * w.z + xv.w * w.w;
    #pragma unroll
    for (int o = 16; o; o >>= 1) {
        a0 += __shfl_xor_sync(0xffffffffu, a0, o);
        a1 += __shfl_xor_sync(0xffffffffu, a1, o);
        a2 += __shfl_xor_sync(0xffffffffu, a2, o);
    }
    if (lane == 0) {
        out[(size_t)gw * 3 + 0] = a0 + b2[0];
        out[(size_t)gw * 3 + 1] = a1 + b2[1];
        out[(size_t)gw * 3 + 2] = a2 + b2[2];
    }
}

// ---------------- launch ----------------
extern "C" void kernel_launch(void* const* d_in, const int* in_sizes, int n_in,
                              void* d_out, int out_size) {
    const float* pos = (const float*)d_in[0];
    const float* nrm = (const float*)d_in[1];
    const int*   ei  = (const int*)d_in[2];
    const float* w1  = (const float*)d_in[3];
    const float* b1  = (const float*)d_in[4];
    const float* w2  = (const float*)d_in[5];
    const float* b2  = (const float*)d_in[6];
    const float* Wg[4] = {(const float*)d_in[7],  (const float*)d_in[11],
                          (const float*)d_in[15], (const float*)d_in[19]};
    const float* u[4]  = {(const float*)d_in[8],  (const float*)d_in[12],
                          (const float*)d_in[16], (const float*)d_in[20]};
    const float* c[4]  = {(const float*)d_in[9],  (const float*)d_in[13],
                          (const float*)d_in[17], (const float*)d_in[21]};
    const float* bg[4] = {(const float*)d_in[10], (const float*)d_in[14],
                          (const float*)d_in[18], (const float*)d_in[22]};

    int n = in_sizes[0] / 3;   // 50000
    int e = in_sizes[2] / 2;   // 800000

    // CSR build
    k_zero_deg<<<(n + 255) / 256, 256>>>(n);
    k_hist<<<(e + 255) / 256, 256>>>(ei, e);
    k_scan<<<1, 1024>>>(n);
    k_scatter<<<(e + 255) / 256, 256>>>(ei, e);

    // weight restack (all layers)
    for (int l = 0; l < 4; l++)
        k_wflat<<<(6 * 128 * 128 + 255) / 256, 256>>>(l, Wg[l]);

    // input layer
    k_x0<<<(n * 128 + 255) / 256, 256>>>(pos, nrm, w1, b1, n);

    // 4 feast layers (ping-pong x between g_x0 / g_x1)
    int sel = 0;
    int warp_blocks = (n * 32 + 255) / 256;
    int edge_blocks = (e + 255) / 256;
    for (int l = 0; l < 4; l++) {
        k_t<<<warp_blocks, 256>>>(sel, u[l], n);
        k_edgeq<<<edge_blocks, 256>>>(c[l], e);
        k_agg<<<warp_blocks, 256>>>(sel, n);
        k_gemm<<<(n + 127) / 128, 256>>>(l, bg[l], 1 - sel);
        sel = 1 - sel;
    }

    // output projection
    k_out<<<warp_blocks, 256>>>(sel, w2, b2, (float*)d_out, n);
}

// round 4
// speedup vs baseline: 1.6900x; 1.5367x over previous
#include <cuda_runtime.h>
#include <cuda_bf16.h>
#include <math.h>
#include <stdint.h>

// ---------------- static scratch (no allocations allowed) ----------------
#define MAXN   50048            // padded
#define MAXE   800000

__device__ float g_x0[MAXN * 128];
__device__ float g_x1[MAXN * 128];
__device__ float g_agg[(size_t)MAXN * 768];
__device__ float g_t[MAXN * 8];          // [N,6] padded to 8 for float4 loads
__device__ float g_q[(size_t)MAXE * 6];  // per-edge softmax (CSR order), pre-scaled by 1/deg
__device__ __nv_bfloat16 g_Bh[4][768 * 128];  // B split hi: [l][n*768+k]
__device__ __nv_bfloat16 g_Bl[4][768 * 128];  // B split lo
__device__ int   g_deg[MAXN];
__device__ int   g_off[MAXN + 1];
__device__ int   g_cur[MAXN];
__device__ int   g_src[MAXE];            // CSR-ordered source ids
__device__ int   g_dst[MAXE];            // CSR-ordered dest ids (for edgeq)

// ---------------- CSR construction ----------------
__global__ void k_zero_deg(int n) {
    int i = blockIdx.x * blockDim.x + threadIdx.x;
    if (i < n) g_deg[i] = 0;
}

__global__ void k_hist(const int* __restrict__ ei, int e) {
    int i = blockIdx.x * blockDim.x + threadIdx.x;
    if (i < e) atomicAdd(&g_deg[ei[e + i]], 1);   // row 1 = dst
}

__global__ void k_scan(int n) {
    __shared__ int sm[1024];
    __shared__ int base;
    if (threadIdx.x == 0) base = 0;
    __syncthreads();
    for (int start = 0; start < n; start += 1024) {
        int i = start + threadIdx.x;
        int v = (i < n) ? g_deg[i] : 0;
        sm[threadIdx.x] = v;
        __syncthreads();
        for (int ofs = 1; ofs < 1024; ofs <<= 1) {
            int t = 0;
            if ((int)threadIdx.x >= ofs) t = sm[threadIdx.x - ofs];
            __syncthreads();
            sm[threadIdx.x] += t;
            __syncthreads();
        }
        if (i < n) {
            int excl = base + sm[threadIdx.x] - v;
            g_off[i] = excl;
            g_cur[i] = excl;
        }
        int total = sm[1023];
        __syncthreads();
        if (threadIdx.x == 0) base += total;
        __syncthreads();
    }
    if (threadIdx.x == 0) g_off[n] = base;
}

__global__ void k_scatter(const int* __restrict__ ei, int e) {
    int i = blockIdx.x * blockDim.x + threadIdx.x;
    if (i < e) {
        int dst = ei[e + i];
        int p = atomicAdd(&g_cur[dst], 1);
        g_src[p] = ei[i];                 // row 0 = src
        g_dst[p] = dst;
    }
}

// ---------------- per-layer weight split: g_Bh/g_Bl[l][n*768+k] = split(Wg[h][n][kk]) ----------------
__global__ void k_wsplit(int l, const float* __restrict__ Wg) {
    int idx = blockIdx.x * blockDim.x + threadIdx.x;
    if (idx >= 768 * 128) return;
    int n = idx / 768, k = idx - n * 768;
    int h = k >> 7, kk = k & 127;
    float v = Wg[h * 16384 + n * 128 + kk];
    __nv_bfloat16 hi = __float2bfloat16_rn(v);
    __nv_bfloat16 lo = __float2bfloat16_rn(v - __bfloat162float(hi));
    g_Bh[l][idx] = hi;
    g_Bl[l][idx] = lo;
}

// ---------------- input layer: x0 = relu([pos,norm] @ w1.T + b1) ----------------
__global__ void k_x0(const float* __restrict__ pos, const float* __restrict__ nrm,
                     const float* __restrict__ w1, const float* __restrict__ b1, int n) {
    int gid = blockIdx.x * blockDim.x + threadIdx.x;
    if (gid >= n * 128) return;
    int i = gid >> 7, d = gid & 127;
    const float* wr = w1 + d * 6;
    float a = b1[d];
    a = fmaf(pos[i * 3 + 0], wr[0], a);
    a = fmaf(pos[i * 3 + 1], wr[1], a);
    a = fmaf(pos[i * 3 + 2], wr[2], a);
    a = fmaf(nrm[i * 3 + 0], wr[3], a);
    a = fmaf(nrm[i * 3 + 1], wr[4], a);
    a = fmaf(nrm[i * 3 + 2], wr[5], a);
    g_x0[(size_t)i * 128 + d] = fmaxf(a, 0.f);
}

// ---------------- t = x @ u.T (per node, warp-per-node) ----------------
__global__ void k_t(int sel, const float* __restrict__ u, int n) {
    int gw = (blockIdx.x * blockDim.x + threadIdx.x) >> 5;
    int lane = threadIdx.x & 31;
    if (gw >= n) return;
    const float* x = sel ? g_x1 : g_x0;
    float4 xv = *(const float4*)(x + (size_t)gw * 128 + lane * 4);
    float a0, a1, a2, a3, a4, a5;
    {
        float4 w;
        w = *(const float4*)(u + 0 * 128 + lane * 4); a0 = xv.x*w.x + xv.y*w.y + xv.z*w.z + xv.w*w.w;
        w = *(const float4*)(u + 1 * 128 + lane * 4); a1 = xv.x*w.x + xv.y*w.y + xv.z*w.z + xv.w*w.w;
        w = *(const float4*)(u + 2 * 128 + lane * 4); a2 = xv.x*w.x + xv.y*w.y + xv.z*w.z + xv.w*w.w;
        w = *(const float4*)(u + 3 * 128 + lane * 4); a3 = xv.x*w.x + xv.y*w.y + xv.z*w.z + xv.w*w.w;
        w = *(const float4*)(u + 4 * 128 + lane * 4); a4 = xv.x*w.x + xv.y*w.y + xv.z*w.z + xv.w*w.w;
        w = *(const float4*)(u + 5 * 128 + lane * 4); a5 = xv.x*w.x + xv.y*w.y + xv.z*w.z + xv.w*w.w;
    }
    #pragma unroll
    for (int o = 16; o; o >>= 1) {
        a0 += __shfl_xor_sync(0xffffffffu, a0, o);
        a1 += __shfl_xor_sync(0xffffffffu, a1, o);
        a2 += __shfl_xor_sync(0xffffffffu, a2, o);
        a3 += __shfl_xor_sync(0xffffffffu, a3, o);
        a4 += __shfl_xor_sync(0xffffffffu, a4, o);
        a5 += __shfl_xor_sync(0xffffffffu, a5, o);
    }
    if (lane == 0) {
        float* tp = g_t + (size_t)gw * 8;
        tp[0] = a0; tp[1] = a1; tp[2] = a2; tp[3] = a3; tp[4] = a4; tp[5] = a5;
        tp[6] = 0.f; tp[7] = 0.f;
    }
}

// ---------------- per-edge softmax (one thread per CSR slot), q pre-scaled by 1/deg ----------------
__global__ void k_edgeq(const float* __restrict__ cvec, int e) {
    int i = blockIdx.x * blockDim.x + threadIdx.x;
    if (i >= e) return;
    int s = g_src[i], d = g_dst[i];
    float4 ts0 = *(const float4*)&g_t[(size_t)s * 8];
    float4 ts1 = *(const float4*)&g_t[(size_t)s * 8 + 4];
    float4 td0 = *(const float4*)&g_t[(size_t)d * 8];
    float4 td1 = *(const float4*)&g_t[(size_t)d * 8 + 4];
    float s0 = ts0.x - td0.x + cvec[0];
    float s1 = ts0.y - td0.y + cvec[1];
    float s2 = ts0.z - td0.z + cvec[2];
    float s3 = ts0.w - td0.w + cvec[3];
    float s4 = ts1.x - td1.x + cvec[4];
    float s5 = ts1.y - td1.y + cvec[5];
    float mx = fmaxf(fmaxf(fmaxf(s0, s1), fmaxf(s2, s3)), fmaxf(s4, s5));
    float e0 = __expf(s0 - mx), e1 = __expf(s1 - mx), e2 = __expf(s2 - mx);
    float e3 = __expf(s3 - mx), e4 = __expf(s4 - mx), e5 = __expf(s5 - mx);
    int deg = g_off[d + 1] - g_off[d];
    float inv = 1.f / ((e0 + e1 + e2 + e3 + e4 + e5) * fmaxf((float)deg, 1.f));
    float* qp = g_q + (size_t)i * 6;
    qp[0] = e0 * inv; qp[1] = e1 * inv; qp[2] = e2 * inv;
    qp[3] = e3 * inv; qp[4] = e4 * inv; qp[5] = e5 * inv;
}

// ---------------- edge aggregation (warp per dst node, no atomics, no softmax) ----------------
__global__ void k_agg(int sel, int n) {
    int gw = (blockIdx.x * blockDim.x + threadIdx.x) >> 5;
    int lane = threadIdx.x & 31;
    if (gw >= n) return;
    const float* x = sel ? g_x1 : g_x0;
    int beg = g_off[gw], end = g_off[gw + 1];
    float4 a0 = make_float4(0,0,0,0), a1 = a0, a2 = a0, a3 = a0, a4 = a0, a5 = a0;
    for (int ep = beg; ep < end; ep++) {
        int s = g_src[ep];
        const float* qp = g_q + (size_t)ep * 6;
        float q0 = qp[0], q1 = qp[1], q2 = qp[2], q3 = qp[3], q4 = qp[4], q5 = qp[5];
        float4 xv = *(const float4*)(x + (size_t)s * 128 + lane * 4);
        a0.x = fmaf(q0, xv.x, a0.x); a0.y = fmaf(q0, xv.y, a0.y); a0.z = fmaf(q0, xv.z, a0.z); a0.w = fmaf(q0, xv.w, a0.w);
        a1.x = fmaf(q1, xv.x, a1.x); a1.y = fmaf(q1, xv.y, a1.y); a1.z = fmaf(q1, xv.z, a1.z); a1.w = fmaf(q1, xv.w, a1.w);
        a2.x = fmaf(q2, xv.x, a2.x); a2.y = fmaf(q2, xv.y, a2.y); a2.z = fmaf(q2, xv.z, a2.z); a2.w = fmaf(q2, xv.w, a2.w);
        a3.x = fmaf(q3, xv.x, a3.x); a3.y = fmaf(q3, xv.y, a3.y); a3.z = fmaf(q3, xv.z, a3.z); a3.w = fmaf(q3, xv.w, a3.w);
        a4.x = fmaf(q4, xv.x, a4.x); a4.y = fmaf(q4, xv.y, a4.y); a4.z = fmaf(q4, xv.z, a4.z); a4.w = fmaf(q4, xv.w, a4.w);
        a5.x = fmaf(q5, xv.x, a5.x); a5.y = fmaf(q5, xv.y, a5.y); a5.z = fmaf(q5, xv.z, a5.z); a5.w = fmaf(q5, xv.w, a5.w);
    }
    float* o = g_agg + (size_t)gw * 768 + lane * 4;
    *(float4*)(o + 0 * 128) = a0;
    *(float4*)(o + 1 * 128) = a1;
    *(float4*)(o + 2 * 128) = a2;
    *(float4*)(o + 3 * 128) = a3;
    *(float4*)(o + 4 * 128) = a4;
    *(float4*)(o + 5 * 128) = a5;
}

// ---------------- mma.sync bf16-split GEMM: x_next = relu(agg[N,768] @ B + bg) ----------------
// CTA: 128x128 tile, K=768 in 24 chunks of 32. 8 warps in 4(M)x2(N) grid; warp = 32x64.
// 3-product split: Ah*Bh + Ah*Bl + Al*Bh accumulated in fp32.
#define LDP 40   // padded smem row stride (bf16 elements); 80B => conflict-free frags

#define MMA_BF16(d, a, b)                                                        \
    asm volatile("mma.sync.aligned.m16n8k16.row.col.f32.bf16.bf16.f32 "          \
        "{%0,%1,%2,%3}, {%4,%5,%6,%7}, {%8,%9}, {%0,%1,%2,%3};"                  \
        : "+f"(d[0]), "+f"(d[1]), "+f"(d[2]), "+f"(d[3])                         \
        : "r"(a[0]), "r"(a[1]), "r"(a[2]), "r"(a[3]), "r"(b[0]), "r"(b[1]))

__global__ void __launch_bounds__(256) k_gemm_mma(int l, const float* __restrict__ bias, int outsel) {
    __shared__ __nv_bfloat16 sA[2][128][LDP];
    __shared__ __nv_bfloat16 sB[2][128][LDP];

    const int tid = threadIdx.x;
    const int wid = tid >> 5, lane = tid & 31;
    const int warpM = wid & 3, warpN = wid >> 2;    // 4 x 2
    const int g = lane >> 2, tig = lane & 3;
    const int blockRow = blockIdx.x * 128;

    const int rowS = tid >> 1, halfS = tid & 1;     // staging: row 0..127, half 0/1
    const float* aptr = g_agg + (size_t)(blockRow + rowS) * 768 + halfS * 16;
    const __nv_bfloat16* bhp = g_Bh[l] + (size_t)rowS * 768 + halfS * 16;
    const __nv_bfloat16* blp = g_Bl[l] + (size_t)rowS * 768 + halfS * 16;

    float acc[2][8][4];
    #pragma unroll
    for (int mt = 0; mt < 2; mt++)
        #pragma unroll
        for (int nt = 0; nt < 8; nt++)
            #pragma unroll
            for (int j = 0; j < 4; j++) acc[mt][nt][j] = 0.f;

    for (int chunk = 0; chunk < 24; chunk++) {
        // --- stage A (convert + split) ---
        const float4* a4 = (const float4*)(aptr + chunk * 32);
        #pragma unroll
        for (int c = 0; c < 4; c++) {
            float4 v = a4[c];
            __nv_bfloat162 h0, h1, lo0, lo1;
            h0.x = __float2bfloat16_rn(v.x); lo0.x = __float2bfloat16_rn(v.x - __bfloat162float(h0.x));
            h0.y = __float2bfloat16_rn(v.y); lo0.y = __float2bfloat16_rn(v.y - __bfloat162float(h0.y));
            h1.x = __float2bfloat16_rn(v.z); lo1.x = __float2bfloat16_rn(v.z - __bfloat162float(h1.x));
            h1.y = __float2bfloat16_rn(v.w); lo1.y = __float2bfloat16_rn(v.w - __bfloat162float(h1.y));
            int col = halfS * 16 + c * 4;
            *(__nv_bfloat162*)&sA[0][rowS][col]     = h0;
            *(__nv_bfloat162*)&sA[0][rowS][col + 2] = h1;
            *(__nv_bfloat162*)&sA[1][rowS][col]     = lo0;
            *(__nv_bfloat162*)&sA[1][rowS][col + 2] = lo1;
        }
        // --- stage B (pre-split copy) ---
        {
            const uint4* sh = (const uint4*)(bhp + chunk * 32);
            const uint4* sl = (const uint4*)(blp + chunk * 32);
            uint4 vh0 = sh[0], vh1 = sh[1];
            uint4 vl0 = sl[0], vl1 = sl[1];
            int col = halfS * 16;
            *(uint4*)&sB[0][rowS][col]     = vh0;
            *(uint4*)&sB[0][rowS][col + 8] = vh1;
            *(uint4*)&sB[1][rowS][col]     = vl0;
            *(uint4*)&sB[1][rowS][col + 8] = vl1;
        }
        __syncthreads();

        #pragma unroll
        for (int kk = 0; kk < 2; kk++) {
            const int kb = kk * 16;
            // A fragments (hi/lo, 2 M-tiles)
            uint32_t aF[2][2][4];
            #pragma unroll
            for (int s = 0; s < 2; s++)
                #pragma unroll
                for (int mt = 0; mt < 2; mt++) {
                    int r = warpM * 32 + mt * 16 + g;
                    const __nv_bfloat16* b0 = &sA[s][r][kb + tig * 2];
                    const __nv_bfloat16* b8 = &sA[s][r + 8][kb + tig * 2];
                    aF[s][mt][0] = *(const uint32_t*)b0;
                    aF[s][mt][1] = *(const uint32_t*)b8;
                    aF[s][mt][2] = *(const uint32_t*)(b0 + 8);
                    aF[s][mt][3] = *(const uint32_t*)(b8 + 8);
                }
            // B fragments (hi/lo, 8 N-tiles)
            uint32_t bF[2][8][2];
            #pragma unroll
            for (int s = 0; s < 2; s++)
                #pragma unroll
                for (int nt = 0; nt < 8; nt++) {
                    int nn = warpN * 64 + nt * 8 + g;
                    const __nv_bfloat16* bb = &sB[s][nn][kb + tig * 2];
                    bF[s][nt][0] = *(const uint32_t*)bb;
                    bF[s][nt][1] = *(const uint32_t*)(bb + 8);
                }
            #pragma unroll
            for (int mt = 0; mt < 2; mt++)
                #pragma unroll
                for (int nt = 0; nt < 8; nt++) {
                    MMA_BF16(acc[mt][nt], aF[0][mt], bF[0][nt]);
                    MMA_BF16(acc[mt][nt], aF[0][mt], bF[1][nt]);
                    MMA_BF16(acc[mt][nt], aF[1][mt], bF[0][nt]);
                }
        }
        __syncthreads();
    }

    // --- epilogue: bias + relu ---
    float* C = outsel ? g_x1 : g_x0;
    #pragma unroll
    for (int mt = 0; mt < 2; mt++) {
        int r0 = blockRow + warpM * 32 + mt * 16 + g;
        #pragma unroll
        for (int nt = 0; nt < 8; nt++) {
            int col = warpN * 64 + nt * 8 + tig * 2;
            float b0 = bias[col], b1 = bias[col + 1];
            float2 v0, v1;
            v0.x = fmaxf(acc[mt][nt][0] + b0, 0.f);
            v0.y = fmaxf(acc[mt][nt][1] + b1, 0.f);
            v1.x = fmaxf(acc[mt][nt][2] + b0, 0.f);
            v1.y = fmaxf(acc[mt][nt][3] + b1, 0.f);
            *(float2*)&C[(size_t)r0 * 128 + col] = v0;
            *(float2*)&C[(size_t)(r0 + 8) * 128 + col] = v1;
        }
    }
}

// ---------------- output: out = x @ w2.T + b2 ----------------
__global__ void k_out(int sel, const float* __restrict__ w2, const float* __restrict__ b2,
                      float* __restrict__ out, int n) {
    int gw = (blockIdx.x * blockDim.x + threadIdx.x) >> 5;
    int lane = threadIdx.x & 31;
    if (gw >= n) return;
    const float* x = sel ? g_x1 : g_x0;
    float4 xv = *(const float4*)(x + (size_t)gw * 128 + lane * 4);
    float4 w;
    w = *(const float4*)(w2 + 0 * 128 + lane * 4);
    float a0 = xv.x * w.x + xv.y * w.y + xv.z * w.z + xv.w * w.w;
    w = *(const float4*)(w2 + 1 * 128 + lane * 4);
    float a1 = xv.x * w.x + xv.y * w.y + xv.z * w.z + xv.w * w.w;
    w = *(const float4*)(w2 + 2 * 128 + lane * 4);
    float a2 = xv.x * w.x + xv.y * w.y + xv.z * w.z + xv.w * w.w;
    #pragma unroll
    for (int o = 16; o; o >>= 1) {
        a0 += __shfl_xor_sync(0xffffffffu, a0, o);
        a1 += __shfl_xor_sync(0xffffffffu, a1, o);
        a2 += __shfl_xor_sync(0xffffffffu, a2, o);
    }
    if (lane == 0) {
        out[(size_t)gw * 3 + 0] = a0 + b2[0];
        out[(size_t)gw * 3 + 1] = a1 + b2[1];
        out[(size_t)gw * 3 + 2] = a2 + b2[2];
    }
}

// ---------------- launch ----------------
extern "C" void kernel_launch(void* const* d_in, const int* in_sizes, int n_in,
                              void* d_out, int out_size) {
    const float* pos = (const float*)d_in[0];
    const float* nrm = (const float*)d_in[1];
    const int*   ei  = (const int*)d_in[2];
    const float* w1  = (const float*)d_in[3];
    const float* b1  = (const float*)d_in[4];
    const float* w2  = (const float*)d_in[5];
    const float* b2  = (const float*)d_in[6];
    const float* Wg[4] = {(const float*)d_in[7],  (const float*)d_in[11],
                          (const float*)d_in[15], (const float*)d_in[19]};
    const float* u[4]  = {(const float*)d_in[8],  (const float*)d_in[12],
                          (const float*)d_in[16], (const float*)d_in[20]};
    const float* c[4]  = {(const float*)d_in[9],  (const float*)d_in[13],
                          (const float*)d_in[17], (const float*)d_in[21]};
    const float* bg[4] = {(const float*)d_in[10], (const float*)d_in[14],
                          (const float*)d_in[18], (const float*)d_in[22]};

    int n = in_sizes[0] / 3;   // 50000
    int e = in_sizes[2] / 2;   // 800000

    // CSR build
    k_zero_deg<<<(n + 255) / 256, 256>>>(n);
    k_hist<<<(e + 255) / 256, 256>>>(ei, e);
    k_scan<<<1, 1024>>>(n);
    k_scatter<<<(e + 255) / 256, 256>>>(ei, e);

    // per-layer weight hi/lo split
    for (int l = 0; l < 4; l++)
        k_wsplit<<<(768 * 128 + 255) / 256, 256>>>(l, Wg[l]);

    // input layer
    k_x0<<<(n * 128 + 255) / 256, 256>>>(pos, nrm, w1, b1, n);

    // 4 feast layers (ping-pong x between g_x0 / g_x1)
    int sel = 0;
    int warp_blocks = (n * 32 + 255) / 256;
    int edge_blocks = (e + 255) / 256;
    int gemm_blocks = (n + 127) / 128;     // 391
    for (int l = 0; l < 4; l++) {
        k_t<<<warp_blocks, 256>>>(sel, u[l], n);
        k_edgeq<<<edge_blocks, 256>>>(c[l], e);
        k_agg<<<warp_blocks, 256>>>(sel, n);
        k_gemm_mma<<<gemm_blocks, 256>>>(l, bg[l], 1 - sel);
        sel = 1 - sel;
    }

    // output projection
    k_out<<<warp_blocks, 256>>>(sel, w2, b2, (float*)d_out, n);
}

// round 5
// speedup vs baseline: 1.7299x; 1.0236x over previous
#include <cuda_runtime.h>
#include <cuda_bf16.h>
#include <math.h>
#include <stdint.h>

// ---------------- static scratch (no allocations allowed) ----------------
#define MAXN   50048            // padded
#define MAXE   800000

__device__ float g_x0[MAXN * 128];
__device__ float g_x1[MAXN * 128];
__device__ __nv_bfloat16 g_Ah[(size_t)MAXN * 768];   // agg hi split (bf16)
__device__ __nv_bfloat16 g_Al[(size_t)MAXN * 768];   // agg lo split
__device__ float g_t[MAXN * 8];          // [N,6] padded to 8
__device__ float g_q[(size_t)MAXE * 8];  // per-edge softmax, padded to 8, pre-scaled 1/deg
__device__ __nv_bfloat16 g_Bh[4][768 * 128];  // B split hi: [l][n*768+k]
__device__ __nv_bfloat16 g_Bl[4][768 * 128];  // B split lo
__device__ int   g_deg[MAXN];
__device__ int   g_off[MAXN + 1];
__device__ int   g_cur[MAXN];
__device__ int   g_src[MAXE];
__device__ int   g_dst[MAXE];

// ---------------- helpers ----------------
__device__ __forceinline__ uint32_t smem_u32(const void* p) {
    uint32_t a;
    asm("{ .reg .u64 t; cvta.to.shared.u64 t, %1; cvt.u32.u64 %0, t; }" : "=r"(a) : "l"(p));
    return a;
}
__device__ __forceinline__ void cpa16(uint32_t dst, const void* src) {
    asm volatile("cp.async.cg.shared.global [%0], [%1], 16;" :: "r"(dst), "l"(src));
}
#define CP_COMMIT() asm volatile("cp.async.commit_group;")
#define LDMX4(r, addr)                                                          \
    asm volatile("ldmatrix.sync.aligned.m8n8.x4.shared.b16 {%0,%1,%2,%3}, [%4];"\
        : "=r"((r)[0]), "=r"((r)[1]), "=r"((r)[2]), "=r"((r)[3]) : "r"(addr))
#define MMA_BF16(d, a, b0, b1)                                                  \
    asm volatile("mma.sync.aligned.m16n8k16.row.col.f32.bf16.bf16.f32 "         \
        "{%0,%1,%2,%3}, {%4,%5,%6,%7}, {%8,%9}, {%0,%1,%2,%3};"                 \
        : "+f"((d)[0]), "+f"((d)[1]), "+f"((d)[2]), "+f"((d)[3])                \
        : "r"((a)[0]), "r"((a)[1]), "r"((a)[2]), "r"((a)[3]), "r"(b0), "r"(b1))

__device__ __forceinline__ uint32_t pack_bf2(float x, float y) {
    __nv_bfloat16 hx = __float2bfloat16_rn(x), hy = __float2bfloat16_rn(y);
    return (uint32_t)__bfloat16_as_ushort(hx) | ((uint32_t)__bfloat16_as_ushort(hy) << 16);
}
// split float4 -> (hi bf16x4 as uint2, lo bf16x4 as uint2)
__device__ __forceinline__ void split4(float4 v, uint2& hi, uint2& lo) {
    __nv_bfloat16 h0 = __float2bfloat16_rn(v.x), h1 = __float2bfloat16_rn(v.y);
    __nv_bfloat16 h2 = __float2bfloat16_rn(v.z), h3 = __float2bfloat16_rn(v.w);
    hi.x = (uint32_t)__bfloat16_as_ushort(h0) | ((uint32_t)__bfloat16_as_ushort(h1) << 16);
    hi.y = (uint32_t)__bfloat16_as_ushort(h2) | ((uint32_t)__bfloat16_as_ushort(h3) << 16);
    lo.x = pack_bf2(v.x - __bfloat162float(h0), v.y - __bfloat162float(h1));
    lo.y = pack_bf2(v.z - __bfloat162float(h2), v.w - __bfloat162float(h3));
}

// ---------------- CSR construction ----------------
__global__ void k_zero_deg(int n) {
    int i = blockIdx.x * blockDim.x + threadIdx.x;
    if (i < n) g_deg[i] = 0;
}
__global__ void k_hist(const int* __restrict__ ei, int e) {
    int i = blockIdx.x * blockDim.x + threadIdx.x;
    if (i < e) atomicAdd(&g_deg[ei[e + i]], 1);
}
__global__ void k_scan(int n) {
    __shared__ int sm[1024];
    __shared__ int base;
    if (threadIdx.x == 0) base = 0;
    __syncthreads();
    for (int start = 0; start < n; start += 1024) {
        int i = start + threadIdx.x;
        int v = (i < n) ? g_deg[i] : 0;
        sm[threadIdx.x] = v;
        __syncthreads();
        for (int ofs = 1; ofs < 1024; ofs <<= 1) {
            int t = 0;
            if ((int)threadIdx.x >= ofs) t = sm[threadIdx.x - ofs];
            __syncthreads();
            sm[threadIdx.x] += t;
            __syncthreads();
        }
        if (i < n) {
            int excl = base + sm[threadIdx.x] - v;
            g_off[i] = excl;
            g_cur[i] = excl;
        }
        int total = sm[1023];
        __syncthreads();
        if (threadIdx.x == 0) base += total;
        __syncthreads();
    }
    if (threadIdx.x == 0) g_off[n] = base;
}
__global__ void k_scatter(const int* __restrict__ ei, int e) {
    int i = blockIdx.x * blockDim.x + threadIdx.x;
    if (i < e) {
        int dst = ei[e + i];
        int p = atomicAdd(&g_cur[dst], 1);
        g_src[p] = ei[i];
        g_dst[p] = dst;
    }
}

// ---------------- per-layer weight split ----------------
__global__ void k_wsplit(int l, const float* __restrict__ Wg) {
    int idx = blockIdx.x * blockDim.x + threadIdx.x;
    if (idx >= 768 * 128) return;
    int n = idx / 768, k = idx - n * 768;
    int h = k >> 7, kk = k & 127;
    float v = Wg[h * 16384 + n * 128 + kk];
    __nv_bfloat16 hi = __float2bfloat16_rn(v);
    g_Bh[l][idx] = hi;
    g_Bl[l][idx] = __float2bfloat16_rn(v - __bfloat162float(hi));
}

// ---------------- input layer ----------------
__global__ void k_x0(const float* __restrict__ pos, const float* __restrict__ nrm,
                     const float* __restrict__ w1, const float* __restrict__ b1, int n) {
    int gid = blockIdx.x * blockDim.x + threadIdx.x;
    if (gid >= n * 128) return;
    int i = gid >> 7, d = gid & 127;
    const float* wr = w1 + d * 6;
    float a = b1[d];
    a = fmaf(pos[i * 3 + 0], wr[0], a);
    a = fmaf(pos[i * 3 + 1], wr[1], a);
    a = fmaf(pos[i * 3 + 2], wr[2], a);
    a = fmaf(nrm[i * 3 + 0], wr[3], a);
    a = fmaf(nrm[i * 3 + 1], wr[4], a);
    a = fmaf(nrm[i * 3 + 2], wr[5], a);
    g_x0[(size_t)i * 128 + d] = fmaxf(a, 0.f);
}

// ---------------- t = x @ u.T ----------------
__global__ void k_t(int sel, const float* __restrict__ u, int n) {
    int gw = (blockIdx.x * blockDim.x + threadIdx.x) >> 5;
    int lane = threadIdx.x & 31;
    if (gw >= n) return;
    const float* x = sel ? g_x1 : g_x0;
    float4 xv = *(const float4*)(x + (size_t)gw * 128 + lane * 4);
    float a0, a1, a2, a3, a4, a5;
    {
        float4 w;
        w = *(const float4*)(u + 0 * 128 + lane * 4); a0 = xv.x*w.x + xv.y*w.y + xv.z*w.z + xv.w*w.w;
        w = *(const float4*)(u + 1 * 128 + lane * 4); a1 = xv.x*w.x + xv.y*w.y + xv.z*w.z + xv.w*w.w;
        w = *(const float4*)(u + 2 * 128 + lane * 4); a2 = xv.x*w.x + xv.y*w.y + xv.z*w.z + xv.w*w.w;
        w = *(const float4*)(u + 3 * 128 + lane * 4); a3 = xv.x*w.x + xv.y*w.y + xv.z*w.z + xv.w*w.w;
        w = *(const float4*)(u + 4 * 128 + lane * 4); a4 = xv.x*w.x + xv.y*w.y + xv.z*w.z + xv.w*w.w;
        w = *(const float4*)(u + 5 * 128 + lane * 4); a5 = xv.x*w.x + xv.y*w.y + xv.z*w.z + xv.w*w.w;
    }
    #pragma unroll
    for (int o = 16; o; o >>= 1) {
        a0 += __shfl_xor_sync(0xffffffffu, a0, o);
        a1 += __shfl_xor_sync(0xffffffffu, a1, o);
        a2 += __shfl_xor_sync(0xffffffffu, a2, o);
        a3 += __shfl_xor_sync(0xffffffffu, a3, o);
        a4 += __shfl_xor_sync(0xffffffffu, a4, o);
        a5 += __shfl_xor_sync(0xffffffffu, a5, o);
    }
    if (lane == 0) {
        float* tp = g_t + (size_t)gw * 8;
        tp[0] = a0; tp[1] = a1; tp[2] = a2; tp[3] = a3; tp[4] = a4; tp[5] = a5;
        tp[6] = 0.f; tp[7] = 0.f;
    }
}

// ---------------- per-edge softmax ----------------
__global__ void k_edgeq(const float* __restrict__ cvec, int e) {
    int i = blockIdx.x * blockDim.x + threadIdx.x;
    if (i >= e) return;
    int s = g_src[i], d = g_dst[i];
    float4 ts0 = *(const float4*)&g_t[(size_t)s * 8];
    float4 ts1 = *(const float4*)&g_t[(size_t)s * 8 + 4];
    float4 td0 = *(const float4*)&g_t[(size_t)d * 8];
    float4 td1 = *(const float4*)&g_t[(size_t)d * 8 + 4];
    float s0 = ts0.x - td0.x + cvec[0];
    float s1 = ts0.y - td0.y + cvec[1];
    float s2 = ts0.z - td0.z + cvec[2];
    float s3 = ts0.w - td0.w + cvec[3];
    float s4 = ts1.x - td1.x + cvec[4];
    float s5 = ts1.y - td1.y + cvec[5];
    float mx = fmaxf(fmaxf(fmaxf(s0, s1), fmaxf(s2, s3)), fmaxf(s4, s5));
    float e0 = __expf(s0 - mx), e1 = __expf(s1 - mx), e2 = __expf(s2 - mx);
    float e3 = __expf(s3 - mx), e4 = __expf(s4 - mx), e5 = __expf(s5 - mx);
    int deg = g_off[d + 1] - g_off[d];
    float inv = 1.f / ((e0 + e1 + e2 + e3 + e4 + e5) * fmaxf((float)deg, 1.f));
    float* qp = g_q + (size_t)i * 8;
    *(float4*)qp       = make_float4(e0 * inv, e1 * inv, e2 * inv, e3 * inv);
    *(float4*)(qp + 4) = make_float4(e4 * inv, e5 * inv, 0.f, 0.f);
}

// ---------------- edge aggregation: unroll-4 MLP, bf16-split output ----------------
#define AGG_FMA(qa, qb, xv)                                                                      \
    do {                                                                                         \
        a0.x = fmaf(qa.x, xv.x, a0.x); a0.y = fmaf(qa.x, xv.y, a0.y);                            \
        a0.z = fmaf(qa.x, xv.z, a0.z); a0.w = fmaf(qa.x, xv.w, a0.w);                            \
        a1.x = fmaf(qa.y, xv.x, a1.x); a1.y = fmaf(qa.y, xv.y, a1.y);                            \
        a1.z = fmaf(qa.y, xv.z, a1.z); a1.w = fmaf(qa.y, xv.w, a1.w);                            \
        a2.x = fmaf(qa.z, xv.x, a2.x); a2.y = fmaf(qa.z, xv.y, a2.y);                            \
        a2.z = fmaf(qa.z, xv.z, a2.z); a2.w = fmaf(qa.z, xv.w, a2.w);                            \
        a3.x = fmaf(qa.w, xv.x, a3.x); a3.y = fmaf(qa.w, xv.y, a3.y);                            \
        a3.z = fmaf(qa.w, xv.z, a3.z); a3.w = fmaf(qa.w, xv.w, a3.w);                            \
        a4.x = fmaf(qb.x, xv.x, a4.x); a4.y = fmaf(qb.x, xv.y, a4.y);                            \
        a4.z = fmaf(qb.x, xv.z, a4.z); a4.w = fmaf(qb.x, xv.w, a4.w);                            \
        a5.x = fmaf(qb.y, xv.x, a5.x); a5.y = fmaf(qb.y, xv.y, a5.y);                            \
        a5.z = fmaf(qb.y, xv.z, a5.z); a5.w = fmaf(qb.y, xv.w, a5.w);                            \
    } while (0)

__global__ void k_agg(int sel, int n) {
    int gw = (blockIdx.x * blockDim.x + threadIdx.x) >> 5;
    int lane = threadIdx.x & 31;
    if (gw >= n) return;
    const float* x = sel ? g_x1 : g_x0;
    int beg = g_off[gw], end = g_off[gw + 1];
    float4 a0 = make_float4(0,0,0,0), a1 = a0, a2 = a0, a3 = a0, a4 = a0, a5 = a0;
    int ep = beg;
    for (; ep + 4 <= end; ep += 4) {
        int s0 = g_src[ep], s1 = g_src[ep + 1], s2 = g_src[ep + 2], s3 = g_src[ep + 3];
        float4 qa0 = *(const float4*)(g_q + (size_t)(ep    ) * 8);
        float4 qb0 = *(const float4*)(g_q + (size_t)(ep    ) * 8 + 4);
        float4 qa1 = *(const float4*)(g_q + (size_t)(ep + 1) * 8);
        float4 qb1 = *(const float4*)(g_q + (size_t)(ep + 1) * 8 + 4);
        float4 qa2 = *(const float4*)(g_q + (size_t)(ep + 2) * 8);
        float4 qb2 = *(const float4*)(g_q + (size_t)(ep + 2) * 8 + 4);
        float4 qa3 = *(const float4*)(g_q + (size_t)(ep + 3) * 8);
        float4 qb3 = *(const float4*)(g_q + (size_t)(ep + 3) * 8 + 4);
        float4 xv0 = *(const float4*)(x + (size_t)s0 * 128 + lane * 4);
        float4 xv1 = *(const float4*)(x + (size_t)s1 * 128 + lane * 4);
        float4 xv2 = *(const float4*)(x + (size_t)s2 * 128 + lane * 4);
        float4 xv3 = *(const float4*)(x + (size_t)s3 * 128 + lane * 4);
        AGG_FMA(qa0, qb0, xv0);
        AGG_FMA(qa1, qb1, xv1);
        AGG_FMA(qa2, qb2, xv2);
        AGG_FMA(qa3, qb3, xv3);
    }
    for (; ep < end; ep++) {
        int s = g_src[ep];
        float4 qa = *(const float4*)(g_q + (size_t)ep * 8);
        float4 qb = *(const float4*)(g_q + (size_t)ep * 8 + 4);
        float4 xv = *(const float4*)(x + (size_t)s * 128 + lane * 4);
        AGG_FMA(qa, qb, xv);
    }
    // write bf16 hi/lo splits: A layout [row][768] = [row][h*128 + d]
    size_t base = (size_t)gw * 768 + lane * 4;
    uint2 hi, lo;
    split4(a0, hi, lo); *(uint2*)(g_Ah + base + 0 * 128) = hi; *(uint2*)(g_Al + base + 0 * 128) = lo;
    split4(a1, hi, lo); *(uint2*)(g_Ah + base + 1 * 128) = hi; *(uint2*)(g_Al + base + 1 * 128) = lo;
    split4(a2, hi, lo); *(uint2*)(g_Ah + base + 2 * 128) = hi; *(uint2*)(g_Al + base + 2 * 128) = lo;
    split4(a3, hi, lo); *(uint2*)(g_Ah + base + 3 * 128) = hi; *(uint2*)(g_Al + base + 3 * 128) = lo;
    split4(a4, hi, lo); *(uint2*)(g_Ah + base + 4 * 128) = hi; *(uint2*)(g_Al + base + 4 * 128) = lo;
    split4(a5, hi, lo); *(uint2*)(g_Ah + base + 5 * 128) = hi; *(uint2*)(g_Al + base + 5 * 128) = lo;
}

// ---------------- GEMM: relu(A[N,768] @ B.T + bias), bf16 3-product split ----------------
// CTA 128x128, BK=16, 48 chunks, 2-stage cp.async, ldmatrix fragments.
// smem [stage][mat][split][row][24] (48B rows: ldmatrix conflict-free, 16B aligned)
#define LDP 24

__global__ void __launch_bounds__(256, 2) k_gemm_mma(int l, const float* __restrict__ bias, int outsel) {
    __shared__ __nv_bfloat16 sm[2][2][2][128][LDP];

    const int tid = threadIdx.x;
    const int wid = tid >> 5, lane = tid & 31;
    const int warpM = wid & 3, warpN = wid >> 2;    // 4 x 2
    const int g = lane >> 2, tig = lane & 3;
    const int blockRow = blockIdx.x * 128;

    const int rowS = tid >> 1, halfS = tid & 1;     // staging: row 0..127, 16B half
    const __nv_bfloat16* gBh = g_Bh[l];
    const __nv_bfloat16* gBl = g_Bl[l];

    float acc[2][8][4];
    #pragma unroll
    for (int mt = 0; mt < 2; mt++)
        #pragma unroll
        for (int nt = 0; nt < 8; nt++)
            #pragma unroll
            for (int j = 0; j < 4; j++) acc[mt][nt][j] = 0.f;

    // ldmatrix lane addressing
    const int lj = lane >> 3, lrr = lane & 7;
    const int lrow = (lj & 1) * 8 + lrr;
    const int lcol = (lj >> 1) * 8;

    // stage loader: chunk c into stage st
    auto stage_load = [&](int c, int st) {
        int k0 = c * 16;
        const __nv_bfloat16* s0 = g_Ah + (size_t)(blockRow + rowS) * 768 + k0 + halfS * 8;
        const __nv_bfloat16* s1 = g_Al + (size_t)(blockRow + rowS) * 768 + k0 + halfS * 8;
        const __nv_bfloat16* s2 = gBh + (size_t)rowS * 768 + k0 + halfS * 8;
        const __nv_bfloat16* s3 = gBl + (size_t)rowS * 768 + k0 + halfS * 8;
        cpa16(smem_u32(&sm[st][0][0][rowS][halfS * 8]), s0);
        cpa16(smem_u32(&sm[st][0][1][rowS][halfS * 8]), s1);
        cpa16(smem_u32(&sm[st][1][0][rowS][halfS * 8]), s2);
        cpa16(smem_u32(&sm[st][1][1][rowS][halfS * 8]), s3);
        CP_COMMIT();
    };

    stage_load(0, 0);

    for (int c = 0; c < 48; c++) {
        int st = c & 1;
        if (c < 47) {
            stage_load(c + 1, st ^ 1);
            asm volatile("cp.async.wait_group 1;");
        } else {
            asm volatile("cp.async.wait_group 0;");
        }
        __syncthreads();

        // A fragments: [split][mt]
        uint32_t aF[2][2][4];
        #pragma unroll
        for (int s = 0; s < 2; s++)
            #pragma unroll
            for (int mt = 0; mt < 2; mt++) {
                uint32_t ad = smem_u32(&sm[st][0][s][warpM * 32 + mt * 16 + lrow][lcol]);
                LDMX4(aF[s][mt], ad);
            }
        #pragma unroll
        for (int ntp = 0; ntp < 4; ntp++) {
            uint32_t bh[4], bl[4];
            LDMX4(bh, smem_u32(&sm[st][1][0][warpN * 64 + ntp * 16 + lrow][lcol]));
            LDMX4(bl, smem_u32(&sm[st][1][1][warpN * 64 + ntp * 16 + lrow][lcol]));
            #pragma unroll
            for (int mt = 0; mt < 2; mt++) {
                float* dE = acc[mt][2 * ntp];
                float* dO = acc[mt][2 * ntp + 1];
                MMA_BF16(dE, aF[0][mt], bh[0], bh[2]);
                MMA_BF16(dE, aF[0][mt], bl[0], bl[2]);
                MMA_BF16(dE, aF[1][mt], bh[0], bh[2]);
                MMA_BF16(dO, aF[0][mt], bh[1], bh[3]);
                MMA_BF16(dO, aF[0][mt], bl[1], bl[3]);
                MMA_BF16(dO, aF[1][mt], bh[1], bh[3]);
            }
        }
        __syncthreads();
    }

    // epilogue
    float* C = outsel ? g_x1 : g_x0;
    #pragma unroll
    for (int mt = 0; mt < 2; mt++) {
        int r0 = blockRow + warpM * 32 + mt * 16 + g;
        #pragma unroll
        for (int nt = 0; nt < 8; nt++) {
            int col = warpN * 64 + nt * 8 + tig * 2;
            float b0 = bias[col], b1 = bias[col + 1];
            float2 v0, v1;
            v0.x = fmaxf(acc[mt][nt][0] + b0, 0.f);
            v0.y = fmaxf(acc[mt][nt][1] + b1, 0.f);
            v1.x = fmaxf(acc[mt][nt][2] + b0, 0.f);
            v1.y = fmaxf(acc[mt][nt][3] + b1, 0.f);
            *(float2*)&C[(size_t)r0 * 128 + col] = v0;
            *(float2*)&C[(size_t)(r0 + 8) * 128 + col] = v1;
        }
    }
}

// ---------------- output: out = x @ w2.T + b2 ----------------
__global__ void k_out(int sel, const float* __restrict__ w2, const float* __restrict__ b2,
                      float* __restrict__ out, int n) {
    int gw = (blockIdx.x * blockDim.x + threadIdx.x) >> 5;
    int lane = threadIdx.x & 31;
    if (gw >= n) return;
    const float* x = sel ? g_x1 : g_x0;
    float4 xv = *(const float4*)(x + (size_t)gw * 128 + lane * 4);
    float4 w;
    w = *(const float4*)(w2 + 0 * 128 + lane * 4);
    float a0 = xv.x * w.x + xv.y * w.y + xv.z * w.z + xv.w * w.w;
    w = *(const float4*)(w2 + 1 * 128 + lane * 4);
    float a1 = xv.x * w.x + xv.y * w.y + xv.z * w.z + xv.w * w.w;
    w = *(const float4*)(w2 + 2 * 128 + lane * 4);
    float a2 = xv.x * w.x + xv.y * w.y + xv.z * w.z + xv.w * w.w;
    #pragma unroll
    for (int o = 16; o; o >>= 1) {
        a0 += __shfl_xor_sync(0xffffffffu, a0, o);
        a1 += __shfl_xor_sync(0xffffffffu, a1, o);
        a2 += __shfl_xor_sync(0xffffffffu, a2, o);
    }
    if (lane == 0) {
        out[(size_t)gw * 3 + 0] = a0 + b2[0];
        out[(size_t)gw * 3 + 1] = a1 + b2[1];
        out[(size_t)gw * 3 + 2] = a2 + b2[2];
    }
}

// ---------------- launch ----------------
extern "C" void kernel_launch(void* const* d_in, const int* in_sizes, int n_in,
                              void* d_out, int out_size) {
    const float* pos = (const float*)d_in[0];
    const float* nrm = (const float*)d_in[1];
    const int*   ei  = (const int*)d_in[2];
    const float* w1  = (const float*)d_in[3];
    const float* b1  = (const float*)d_in[4];
    const float* w2  = (const float*)d_in[5];
    const float* b2  = (const float*)d_in[6];
    const float* Wg[4] = {(const float*)d_in[7],  (const float*)d_in[11],
                          (const float*)d_in[15], (const float*)d_in[19]};
    const float* u[4]  = {(const float*)d_in[8],  (const float*)d_in[12],
                          (const float*)d_in[16], (const float*)d_in[20]};
    const float* c[4]  = {(const float*)d_in[9],  (const float*)d_in[13],
                          (const float*)d_in[17], (const float*)d_in[21]};
    const float* bg[4] = {(const float*)d_in[10], (const float*)d_in[14],
                          (const float*)d_in[18], (const float*)d_in[22]};

    int n = in_sizes[0] / 3;   // 50000
    int e = in_sizes[2] / 2;   // 800000

    // CSR build
    k_zero_deg<<<(n + 255) / 256, 256>>>(n);
    k_hist<<<(e + 255) / 256, 256>>>(ei, e);
    k_scan<<<1, 1024>>>(n);
    k_scatter<<<(e + 255) / 256, 256>>>(ei, e);

    // per-layer weight hi/lo split
    for (int l = 0; l < 4; l++)
        k_wsplit<<<(768 * 128 + 255) / 256, 256>>>(l, Wg[l]);

    // input layer
    k_x0<<<(n * 128 + 255) / 256, 256>>>(pos, nrm, w1, b1, n);

    // 4 feast layers (ping-pong x between g_x0 / g_x1)
    int sel = 0;
    int warp_blocks = (n * 32 + 255) / 256;
    int edge_blocks = (e + 255) / 256;
    int gemm_blocks = (n + 127) / 128;     // 391
    for (int l = 0; l < 4; l++) {
        k_t<<<warp_blocks, 256>>>(sel, u[l], n);
        k_edgeq<<<edge_blocks, 256>>>(c[l], e);
        k_agg<<<warp_blocks, 256>>>(sel, n);
        k_gemm_mma<<<gemm_blocks, 256>>>(l, bg[l], 1 - sel);
        sel = 1 - sel;
    }

    // output projection
    k_out<<<warp_blocks, 256>>>(sel, w2, b2, (float*)d_out, n);
}